// round 12
// baseline (speedup 1.0000x reference)
#include <cuda_runtime.h>
#include <math.h>

#define NW    296
#define XPAD  300           // padded xe row (bank-conflict-free LDS.128 phases)
#define FMD   74
#define NBIN  2701          // 74*73/2
#define NBINP 2816          // 11 * 256 (padded; pad weights stay zero)
#define NBP   (NBINP/2)     // 1408 bin-pairs
#define CHUNK 256
#define NCHUNK 11
#define NHEAD 64
#define NEMB  48
#define RB    8             // rows per block
#define SEGS  8
#define SEGLEN ((NBIN + SEGS - 1) / SEGS)   // 338

// __device__ scratch (zero-initialized at module load; pads never written)
__device__ float g_wA2[NBP * 128];          // [bpair][head][2bins], = (wNDI[h,I,J]-wNDI[h,J,I])/16
__device__ float g_wDIeff[FMD * NHEAD];     // (colsum-rowsum)/4, K-major
__device__ unsigned short g_binIJ[NBIN];    // (I<<8)|J

__device__ __forceinline__ float elu1(float v) { return v > 0.f ? v : expm1f(v); }

__device__ __forceinline__ unsigned long long pk2(float a, float b) {
    unsigned long long r;
    asm("mov.b64 %0, {%1, %2};" : "=l"(r) : "f"(a), "f"(b));
    return r;
}
__device__ __forceinline__ void upk2(float& a, float& b, unsigned long long v) {
    asm("mov.b64 {%0, %1}, %2;" : "=f"(a), "=f"(b) : "l"(v));
}
// packed dual-FMA: only reachable via PTX fma.rn.f32x2
__device__ __forceinline__ void ffma2(unsigned long long& d, unsigned long long a, unsigned long long b) {
    asm("fma.rn.f32x2 %0, %1, %2, %0;" : "+l"(d) : "l"(a), "l"(b));
}

// ---------------- prep: build effective weights + LUT ----------------
__global__ __launch_bounds__(256) void prep_kernel(const float* __restrict__ wDI,
                                                   const float* __restrict__ wNDI) {
    __shared__ float w[FMD * FMD];
    int blk = blockIdx.x;
    int tid = threadIdx.x;
    if (blk < NHEAD * SEGS) {
        int h = blk >> 3, seg = blk & (SEGS - 1);
        const float* src = wNDI + h * FMD * FMD;
        for (int i = tid; i < FMD * FMD; i += 256) w[i] = src[i];
        __syncthreads();
        int t0 = seg * SEGLEN, t1 = min(NBIN, t0 + SEGLEN);
        for (int t = t0 + tid; t < t1; t += 256) {
            int I = (int)((147.0f - sqrtf(147.0f * 147.0f - 8.0f * (float)t)) * 0.5f);
            I = max(0, min(72, I));
            while (I > 0 && (I * 73 - (I * (I - 1)) / 2) > t) I--;
            while (I < 72 && ((I + 1) * 73 - ((I + 1) * I) / 2) <= t) I++;
            int J = I + 1 + (t - (I * 73 - (I * (I - 1)) / 2));
            // [bpair][head][bin-parity]
            g_wA2[(t >> 1) * 128 + h * 2 + (t & 1)] =
                (w[I * FMD + J] - w[J * FMD + I]) * (1.0f / 16.0f);
            if (h == 0) g_binIJ[t] = (unsigned short)((I << 8) | J);
        }
    } else {
        int h = blk - NHEAD * SEGS;
        const float* src = wDI + h * FMD * FMD;
        for (int i = tid; i < FMD * FMD; i += 256) w[i] = src[i];
        __syncthreads();
        if (tid < FMD) {
            float cs = 0.f, rs = 0.f;
            #pragma unroll 2
            for (int I = 0; I < FMD; I++) {
                cs += w[I * FMD + tid];
                rs += w[tid * FMD + I];
            }
            g_wDIeff[tid * NHEAD + h] = (cs - rs) * 0.25f;
        }
    }
}

// ---------------- fused: on-the-fly pool + contraction + MLP tail ----------------
struct TailS {
    float hN[RB][NHEAD];
    float hD[RB][NHEAD];
    float emb[RB][2 * NEMB];
    float z1[RB][NEMB];
    float z2[RB][20];
};
union BigU {
    struct {
        float xe[RB][XPAD];        // 9600 B, conflict-free rows
        float ps3[2][128][16];     // 16384 B: [buf][bpair][row*2+parity]
    } a;
    unsigned long long redu[4][RB][32];   // 8192 B slot-reduction (slot, row, head-pair)
    float redf[4][RB][NHEAD];             // float view
};

__global__ __launch_bounds__(512, 3) void fused_kernel(
    const float* __restrict__ x,
    const float* __restrict__ bDI,   const float* __restrict__ fcDI_w,  const float* __restrict__ fcDI_b,
    const float* __restrict__ bNDI,  const float* __restrict__ fcNDI_w, const float* __restrict__ fcNDI_b,
    const float* __restrict__ fc1_w, const float* __restrict__ fc1_b,
    const float* __restrict__ l1_w,  const float* __restrict__ l1_b,
    const float* __restrict__ l2_w,  const float* __restrict__ l2_b,
    float* __restrict__ out)
{
    __shared__ BigU u;
    __shared__ TailS t;
    __shared__ float sus[RB][FMD];
    __shared__ unsigned short sIJ[NBINP];

    int tid  = threadIdx.x;
    int row0 = blockIdx.x * RB;

    // consumer mapping: 32 head-pairs x 4 bpair-slots x 4 row-groups (2 rows each)
    int hp   = tid & 31;          // heads 2hp, 2hp+1
    int slot = (tid >> 5) & 3;    // 32 consecutive bpairs per slot
    int rgrp = tid >> 7;          // 0..3, rows 2*rgrp, 2*rgrp+1

    // stage 0: LUT (zero-padded) + x rows (+eps/2 folded in)
    for (int i = tid; i < NBINP; i += 512) sIJ[i] = (i < NBIN) ? g_binIJ[i] : (unsigned short)0;
    for (int i = tid; i < RB * NW; i += 512) {
        int r = i / NW, c = i % NW;
        u.a.xe[r][c] = x[(size_t)(row0 + r) * 300 + c] + 5e-6f;
    }
    __syncthreads();
    // group sums — RB*FMD = 592 > 512: strided loop required
    for (int i = tid; i < RB * FMD; i += 512) {
        int r = i / FMD, K = i % FMD;
        float4 v = ((const float4*)u.a.xe[r])[K];
        sus[r][K] = v.x + v.y + v.z + v.w;
    }

    // ---- pooled-NDI producer: one 256-bin chunk -> ps3[buf][bpair][r*2+par]
    // Sum_i (xj-ai)/(xj+ai) = 2xj * Sum_i 1/s_i - 4  ->  1 rcp per (bin, j)
    #define STAGE1(C0, BUF)                                                         \
    {                                                                               \
        int rr = tid & 7;                                                           \
        int bq = tid >> 3;                                                          \
        const float4* xs4 = (const float4*)u.a.xe[rr];                              \
        _Pragma("unroll")                                                           \
        for (int it = 0; it < 4; it++) {                                            \
            int b = bq + it * 64;                                                   \
            unsigned ij = sIJ[(C0) + b];                                            \
            float4 ga = xs4[ij >> 8];                                               \
            float4 gb = xs4[ij & 255];                                              \
            float av[4] = {ga.x, ga.y, ga.z, ga.w};                                 \
            float bv[4] = {gb.x, gb.y, gb.z, gb.w};                                 \
            float acc = -16.0f;                                                     \
            _Pragma("unroll")                                                       \
            for (int j = 0; j < 4; j++) {                                           \
                float xj = bv[j];                                                   \
                float s0 = av[0] + xj, s1 = av[1] + xj;                             \
                float s2 = av[2] + xj, s3 = av[3] + xj;                             \
                float t01 = s0 * s1, t23 = s2 * s3;                                 \
                float n01 = s0 + s1, n23 = s2 + s3;                                 \
                float num = fmaf(n01, t23, n23 * t01);                              \
                float den = t01 * t23;                                              \
                float y;                                                            \
                asm("rcp.approx.f32 %0, %1;" : "=f"(y) : "f"(den));                 \
                acc = fmaf(xj + xj, num * y, acc);                                  \
            }                                                                       \
            u.a.ps3[BUF][b >> 1][(rr << 1) | (b & 1)] = acc;                        \
        }                                                                           \
    }

    // accs: bins packed in f32x2 lanes; [head][row]
    unsigned long long a00 = 0ull, a01 = 0ull, a10 = 0ull, a11 = 0ull;

    STAGE1(0, 0);
    __syncthreads();
    for (int c = 0; c < NCHUNK; c++) {
        int buf = c & 1;
        int c0 = c << 8;
        if (c < NCHUNK - 1) STAGE1(c0 + CHUNK, buf ^ 1);
        // consumer: 32 bpairs/thread; LDG.128 w = {b0h0,b1h0,b0h1,b1h1}; LDS.128 p broadcast
        const float* wp = g_wA2 + ((size_t)(c0 >> 1) + 32 * slot) * 128 + 4 * hp;
        const ulonglong2* pp = (const ulonglong2*)&u.a.ps3[buf][32 * slot][4 * rgrp];
        #pragma unroll 8
        for (int i = 0; i < 32; i++) {
            ulonglong2 w = *(const ulonglong2*)(wp + (size_t)i * 128);
            ulonglong2 p = pp[(size_t)i * 4];   // bpair stride = 16 floats = 4 ulonglong2
            ffma2(a00, p.x, w.x);   // row 2rgrp,   heads 2hp (bins b0,b1 in lanes)
            ffma2(a01, p.x, w.y);   // row 2rgrp,   head 2hp+1
            ffma2(a10, p.y, w.x);   // row 2rgrp+1, head 2hp
            ffma2(a11, p.y, w.y);   // row 2rgrp+1, head 2hp+1
        }
        __syncthreads();
    }

    // ---- fold bin-parity lanes, reduce 4 slots via aliased smem (xe/ps3 dead now)
    {
        float lo, hi;
        float s00, s01, s10, s11;
        upk2(lo, hi, a00); s00 = lo + hi;
        upk2(lo, hi, a01); s01 = lo + hi;
        upk2(lo, hi, a10); s10 = lo + hi;
        upk2(lo, hi, a11); s11 = lo + hi;
        int r0 = 2 * rgrp;
        u.redu[slot][r0 + 0][hp] = pk2(s00, s01);   // heads 2hp,2hp+1 adjacent
        u.redu[slot][r0 + 1][hp] = pk2(s10, s11);
    }
    __syncthreads();

    // one thread per (row, head): NDI reduce + bias + elu; DI head full dot
    {
        int r = tid >> 6, h = tid & 63;
        float s = u.redf[0][r][h] + u.redf[1][r][h] + u.redf[2][r][h] + u.redf[3][r][h];
        t.hN[r][h] = elu1(s + bNDI[h]);

        float d = 0.f;
        #pragma unroll 2
        for (int K = 0; K < FMD; K++)
            d = fmaf(sus[r][K], g_wDIeff[K * NHEAD + h], d);
        t.hD[r][h] = elu1(d + bDI[h]);
    }
    __syncthreads();

    // eDI / eNDI (48 each) -> emb[96]
    if (tid < RB * NEMB) {
        int r = tid / NEMB, e = tid % NEMB;
        float v = fcDI_b[e], v2 = fcNDI_b[e];
        #pragma unroll 8
        for (int h = 0; h < NHEAD; h++) {
            v  = fmaf(fcDI_w[e * NHEAD + h],  t.hD[r][h], v);
            v2 = fmaf(fcNDI_w[e * NHEAD + h], t.hN[r][h], v2);
        }
        t.emb[r][e]        = elu1(v);
        t.emb[r][NEMB + e] = elu1(v2);
    }
    __syncthreads();

    // fc1: 96 -> 48
    if (tid < RB * NEMB) {
        int r = tid / NEMB, o = tid % NEMB;
        float v = fc1_b[o];
        #pragma unroll 8
        for (int c = 0; c < 2 * NEMB; c++) v = fmaf(fc1_w[o * 2 * NEMB + c], t.emb[r][c], v);
        t.z1[r][o] = elu1(v);
    }
    __syncthreads();

    // l1: 48 -> 20
    if (tid < RB * 20) {
        int r = tid / 20, o = tid % 20;
        float v = l1_b[o];
        #pragma unroll 8
        for (int c = 0; c < NEMB; c++) v = fmaf(l1_w[o * NEMB + c], t.z1[r][c], v);
        t.z2[r][o] = elu1(v);
    }
    __syncthreads();

    // l2: 20 -> 1, sigmoid
    if (tid < RB) {
        float v = l2_b[0];
        #pragma unroll
        for (int c = 0; c < 20; c++) v = fmaf(l2_w[c], t.z2[tid][c], v);
        out[row0 + tid] = 1.0f / (1.0f + expf(-v));
    }
}

extern "C" void kernel_launch(void* const* d_in, const int* in_sizes, int n_in,
                              void* d_out, int out_size) {
    const float* x       = (const float*)d_in[0];
    const float* wDI     = (const float*)d_in[1];
    const float* bDI     = (const float*)d_in[2];
    const float* fcDI_w  = (const float*)d_in[3];
    const float* fcDI_b  = (const float*)d_in[4];
    const float* wNDI    = (const float*)d_in[5];
    const float* bNDI    = (const float*)d_in[6];
    const float* fcNDI_w = (const float*)d_in[7];
    const float* fcNDI_b = (const float*)d_in[8];
    const float* fc1_w   = (const float*)d_in[9];
    const float* fc1_b   = (const float*)d_in[10];
    const float* l1_w    = (const float*)d_in[11];
    const float* l1_b    = (const float*)d_in[12];
    const float* l2_w    = (const float*)d_in[13];
    const float* l2_b    = (const float*)d_in[14];
    float* out = (float*)d_out;

    int B = in_sizes[0] / 300;   // 2048

    prep_kernel<<<NHEAD * SEGS + NHEAD, 256>>>(wDI, wNDI);
    fused_kernel<<<B / RB, 512>>>(x, bDI, fcDI_w, fcDI_b, bNDI, fcNDI_w, fcNDI_b,
                                  fc1_w, fc1_b, l1_w, l1_b, l2_w, l2_b, out);
}

// round 13
// speedup vs baseline: 1.0505x; 1.0505x over previous
#include <cuda_runtime.h>
#include <math.h>

#define NW    296
#define FMD   74
#define NBIN  2701          // 74*73/2
#define NBINP 2816          // 11 * 256 (padded; pad weights/P stay zero)
#define NHEAD 64
#define NEMB  48
#define RB    8
#define SEGS  8
#define SEGLEN ((NBIN + SEGS - 1) / SEGS)   // 338
#define BMAX  2048
// GEMM tiling
#define BM 32
#define BN 64
#define BK 32
#define KSPL 11
#define KLEN (NBINP / KSPL)   // 256 = 8 BK-steps

// __device__ scratch (zero-initialized at module load)
__device__ float g_wA[NBINP * NHEAD];       // [bin][head] = (wNDI[h,I,J]-wNDI[h,J,I])/16
__device__ float g_wDIeff[FMD * NHEAD];     // (colsum-rowsum)/4, K-major
__device__ unsigned short g_binIJ[NBIN];    // (I<<8)|J
__device__ float g_U[BMAX * FMD];           // group sums
__device__ float g_P[BMAX * NBINP];         // pooled NDI (raw 16-pair sums), pad = 0
__device__ float g_Hp[KSPL * BMAX * NHEAD]; // GEMM partials

__device__ __forceinline__ float elu1(float v) { return v > 0.f ? v : expm1f(v); }

__device__ __forceinline__ unsigned long long pk2(float a, float b) {
    unsigned long long r;
    asm("mov.b64 %0, {%1, %2};" : "=l"(r) : "f"(a), "f"(b));
    return r;
}
__device__ __forceinline__ void upk2(float& a, float& b, unsigned long long v) {
    asm("mov.b64 {%0, %1}, %2;" : "=f"(a), "=f"(b) : "l"(v));
}
// packed dual-FMA via PTX fma.rn.f32x2 (ptxas never auto-fuses)
__device__ __forceinline__ void ffma2(unsigned long long& d, unsigned long long a, unsigned long long b) {
    asm("fma.rn.f32x2 %0, %1, %2, %0;" : "+l"(d) : "l"(a), "l"(b));
}

// ---------------- prep: build effective weights + LUT ----------------
__global__ __launch_bounds__(256) void prep_kernel(const float* __restrict__ wDI,
                                                   const float* __restrict__ wNDI) {
    __shared__ float w[FMD * FMD];
    int blk = blockIdx.x;
    int tid = threadIdx.x;
    if (blk < NHEAD * SEGS) {
        int h = blk >> 3, seg = blk & (SEGS - 1);
        const float* src = wNDI + h * FMD * FMD;
        for (int i = tid; i < FMD * FMD; i += 256) w[i] = src[i];
        __syncthreads();
        int t0 = seg * SEGLEN, t1 = min(NBIN, t0 + SEGLEN);
        for (int t = t0 + tid; t < t1; t += 256) {
            int I = (int)((147.0f - sqrtf(147.0f * 147.0f - 8.0f * (float)t)) * 0.5f);
            I = max(0, min(72, I));
            while (I > 0 && (I * 73 - (I * (I - 1)) / 2) > t) I--;
            while (I < 72 && ((I + 1) * 73 - ((I + 1) * I) / 2) <= t) I++;
            int J = I + 1 + (t - (I * 73 - (I * (I - 1)) / 2));
            g_wA[t * NHEAD + h] = (w[I * FMD + J] - w[J * FMD + I]) * (1.0f / 16.0f);
            if (h == 0) g_binIJ[t] = (unsigned short)((I << 8) | J);
        }
    } else {
        int h = blk - NHEAD * SEGS;
        const float* src = wDI + h * FMD * FMD;
        for (int i = tid; i < FMD * FMD; i += 256) w[i] = src[i];
        __syncthreads();
        if (tid < FMD) {
            float cs = 0.f, rs = 0.f;
            #pragma unroll 2
            for (int I = 0; I < FMD; I++) {
                cs += w[I * FMD + tid];
                rs += w[tid * FMD + I];
            }
            g_wDIeff[tid * NHEAD + h] = (cs - rs) * 0.25f;
        }
    }
}

// ---------------- pool: per-row pooled NDI, barrier-free after x load ----------------
__global__ __launch_bounds__(256) void pool_kernel(const float* __restrict__ x) {
    __shared__ __align__(16) float xe[NW];
    int row = blockIdx.x;
    int tid = threadIdx.x;
    const float* xr = x + (size_t)row * 300;
    for (int i = tid; i < NW; i += 256) xe[i] = xr[i] + 5e-6f;   // eps/2 folded
    __syncthreads();
    if (tid < FMD) {
        float4 v = ((const float4*)xe)[tid];
        g_U[row * FMD + tid] = v.x + v.y + v.z + v.w;
    }
    const float4* xs4 = (const float4*)xe;
    for (int b = tid; b < NBINP; b += 256) {
        float acc = 0.f;
        if (b < NBIN) {
            unsigned ij = g_binIJ[b];
            float4 ga = xs4[ij >> 8];
            float4 gb = xs4[ij & 255];
            float av[4] = {ga.x, ga.y, ga.z, ga.w};
            float bv[4] = {gb.x, gb.y, gb.z, gb.w};
            // Sum_i (xj-ai)/(xj+ai) = 2xj * Sum_i 1/s_i - 4  (1 rcp per j)
            acc = -16.0f;
            #pragma unroll
            for (int j = 0; j < 4; j++) {
                float xj = bv[j];
                float s0 = av[0] + xj, s1 = av[1] + xj;
                float s2 = av[2] + xj, s3 = av[3] + xj;
                float t01 = s0 * s1, t23 = s2 * s3;
                float num = fmaf(s0 + s1, t23, (s2 + s3) * t01);
                float den = t01 * t23;
                float y;
                asm("rcp.approx.f32 %0, %1;" : "=f"(y) : "f"(den));
                acc = fmaf(xj + xj, num * y, acc);
            }
        }
        g_P[(size_t)row * NBINP + b] = acc;   // pad bins written as 0 (deterministic)
    }
}

// ---------------- gemm: H = P[2048 x 2816] . wA[2816 x 64], K-split partials ----------------
__global__ __launch_bounds__(256) void gemm_kernel() {
    __shared__ float As[BK][BM + 2];   // +2 keeps u64 alignment, spreads banks
    __shared__ float Bs[BK][BN];
    int tid = threadIdx.x;
    int m0  = blockIdx.x * BM;
    int k0  = blockIdx.y * KLEN;
    // load mapping
    int lrow = tid >> 3;            // 0..31 P-row within tile
    int lcol = (tid & 7) * 4;       // bin within BK
    int lk   = tid >> 3;            // 0..31 wA k
    int lh   = (tid & 7) * 8;       // head
    // compute mapping: 2 rows x 4 heads per thread
    int hg = tid & 15;              // heads 4hg..4hg+3
    int rg = tid >> 4;              // rows 2rg, 2rg+1

    unsigned long long acc0 = 0ull, acc1 = 0ull, acc2 = 0ull, acc3 = 0ull;

    for (int kk = 0; kk < KLEN; kk += BK) {
        float4 pv = *(const float4*)&g_P[(size_t)(m0 + lrow) * NBINP + k0 + kk + lcol];
        float4 w0 = *(const float4*)&g_wA[(size_t)(k0 + kk + lk) * NHEAD + lh];
        float4 w1 = *(const float4*)&g_wA[(size_t)(k0 + kk + lk) * NHEAD + lh + 4];
        __syncthreads();
        As[lcol + 0][lrow] = pv.x;
        As[lcol + 1][lrow] = pv.y;
        As[lcol + 2][lrow] = pv.z;
        As[lcol + 3][lrow] = pv.w;
        *(float4*)&Bs[lk][lh]     = w0;
        *(float4*)&Bs[lk][lh + 4] = w1;
        __syncthreads();
        #pragma unroll
        for (int k = 0; k < BK; k++) {
            unsigned long long a = *(const unsigned long long*)&As[k][2 * rg];  // {r0,r1}
            float4 bv = *(const float4*)&Bs[k][4 * hg];
            ffma2(acc0, a, pk2(bv.x, bv.x));
            ffma2(acc1, a, pk2(bv.y, bv.y));
            ffma2(acc2, a, pk2(bv.z, bv.z));
            ffma2(acc3, a, pk2(bv.w, bv.w));
        }
    }
    float r00, r10, r01, r11, r02, r12, r03, r13;
    upk2(r00, r10, acc0); upk2(r01, r11, acc1);
    upk2(r02, r12, acc2); upk2(r03, r13, acc3);
    size_t base = ((size_t)blockIdx.y * BMAX + m0 + 2 * rg) * NHEAD + 4 * hg;
    *(float4*)&g_Hp[base]         = make_float4(r00, r01, r02, r03);
    *(float4*)&g_Hp[base + NHEAD] = make_float4(r10, r11, r12, r13);
}

// ---------------- tail: partial-reduce + DI head + MLP (validated R10 code path) ----------------
struct TailS {
    float hN[RB][NHEAD];
    float hD[RB][NHEAD];
    float emb[RB][2 * NEMB];
    float z1[RB][NEMB];
    float z2[RB][20];
};

__global__ __launch_bounds__(512) void tail_kernel(
    const float* __restrict__ bDI,   const float* __restrict__ fcDI_w,  const float* __restrict__ fcDI_b,
    const float* __restrict__ bNDI,  const float* __restrict__ fcNDI_w, const float* __restrict__ fcNDI_b,
    const float* __restrict__ fc1_w, const float* __restrict__ fc1_b,
    const float* __restrict__ l1_w,  const float* __restrict__ l1_b,
    const float* __restrict__ l2_w,  const float* __restrict__ l2_b,
    float* __restrict__ out)
{
    __shared__ TailS t;
    __shared__ float sus[RB][FMD];
    int tid  = threadIdx.x;
    int row0 = blockIdx.x * RB;

    for (int i = tid; i < RB * FMD; i += 512) {
        int r = i / FMD, K = i % FMD;
        sus[r][K] = g_U[(row0 + r) * FMD + K];
    }
    __syncthreads();

    {   // 512 threads = 8 rows x 64 heads exactly
        int r = tid >> 6, h = tid & 63;
        float s = bNDI[h];
        #pragma unroll
        for (int ks = 0; ks < KSPL; ks++)
            s += g_Hp[((size_t)ks * BMAX + row0 + r) * NHEAD + h];
        t.hN[r][h] = elu1(s);

        float d = 0.f;
        #pragma unroll 2
        for (int K = 0; K < FMD; K++)
            d = fmaf(sus[r][K], g_wDIeff[K * NHEAD + h], d);
        t.hD[r][h] = elu1(d + bDI[h]);
    }
    __syncthreads();

    // eDI / eNDI (48 each) -> emb[96]
    if (tid < RB * NEMB) {
        int r = tid / NEMB, e = tid % NEMB;
        float v = fcDI_b[e], v2 = fcNDI_b[e];
        #pragma unroll 8
        for (int h = 0; h < NHEAD; h++) {
            v  = fmaf(fcDI_w[e * NHEAD + h],  t.hD[r][h], v);
            v2 = fmaf(fcNDI_w[e * NHEAD + h], t.hN[r][h], v2);
        }
        t.emb[r][e]        = elu1(v);
        t.emb[r][NEMB + e] = elu1(v2);
    }
    __syncthreads();

    // fc1: 96 -> 48
    if (tid < RB * NEMB) {
        int r = tid / NEMB, o = tid % NEMB;
        float v = fc1_b[o];
        #pragma unroll 8
        for (int c = 0; c < 2 * NEMB; c++) v = fmaf(fc1_w[o * 2 * NEMB + c], t.emb[r][c], v);
        t.z1[r][o] = elu1(v);
    }
    __syncthreads();

    // l1: 48 -> 20
    if (tid < RB * 20) {
        int r = tid / 20, o = tid % 20;
        float v = l1_b[o];
        #pragma unroll 8
        for (int c = 0; c < NEMB; c++) v = fmaf(l1_w[o * NEMB + c], t.z1[r][c], v);
        t.z2[r][o] = elu1(v);
    }
    __syncthreads();

    // l2: 20 -> 1, sigmoid
    if (tid < RB) {
        float v = l2_b[0];
        #pragma unroll
        for (int c = 0; c < 20; c++) v = fmaf(l2_w[c], t.z2[tid][c], v);
        out[row0 + tid] = 1.0f / (1.0f + expf(-v));
    }
}

extern "C" void kernel_launch(void* const* d_in, const int* in_sizes, int n_in,
                              void* d_out, int out_size) {
    const float* x       = (const float*)d_in[0];
    const float* wDI     = (const float*)d_in[1];
    const float* bDI     = (const float*)d_in[2];
    const float* fcDI_w  = (const float*)d_in[3];
    const float* fcDI_b  = (const float*)d_in[4];
    const float* wNDI    = (const float*)d_in[5];
    const float* bNDI    = (const float*)d_in[6];
    const float* fcNDI_w = (const float*)d_in[7];
    const float* fcNDI_b = (const float*)d_in[8];
    const float* fc1_w   = (const float*)d_in[9];
    const float* fc1_b   = (const float*)d_in[10];
    const float* l1_w    = (const float*)d_in[11];
    const float* l1_b    = (const float*)d_in[12];
    const float* l2_w    = (const float*)d_in[13];
    const float* l2_b    = (const float*)d_in[14];
    float* out = (float*)d_out;

    int B = in_sizes[0] / 300;   // 2048

    prep_kernel<<<NHEAD * SEGS + NHEAD, 256>>>(wDI, wNDI);
    pool_kernel<<<B, 256>>>(x);
    gemm_kernel<<<dim3(B / BM, KSPL), 256>>>();
    tail_kernel<<<B / RB, 512>>>(bDI, fcDI_w, fcDI_b, bNDI, fcNDI_w, fcNDI_b,
                                 fc1_w, fc1_b, l1_w, l1_b, l2_w, l2_b, out);
}

// round 14
// speedup vs baseline: 1.8113x; 1.7243x over previous
#include <cuda_runtime.h>
#include <math.h>

#define NW    296
#define FMD   74
#define NBIN  2701          // 74*73/2
#define NBINP 2816          // 11 * 256 (padded; pad weights/P stay zero)
#define NHEAD 64
#define NEMB  48
#define RB    8
#define SEGS  8
#define SEGLEN ((NBIN + SEGS - 1) / SEGS)   // 338
#define BMAX  2048
// GEMM tiling
#define BM 32
#define BN 64
#define BK 32
#define KSPL 11
#define KLEN (NBINP / KSPL)   // 256 = 8 BK-steps

// __device__ scratch (zero-initialized at module load)
__device__ float g_wA[NBINP * NHEAD];       // [bin][head] = (wNDI[h,I,J]-wNDI[h,J,I])/16
__device__ float g_wDIeff[FMD * NHEAD];     // (colsum-rowsum)/4, K-major
__device__ unsigned short g_binIJ[NBIN];    // (I<<8)|J
__device__ float g_U[BMAX * FMD];           // group sums
__device__ float g_P[BMAX * NBINP];         // pooled NDI (raw 16-pair sums), pad = 0
__device__ float g_Hp[KSPL * BMAX * NHEAD]; // GEMM partials
// transposed MLP weights (coalesced tail reads: output index lane-varying)
__device__ float g_fcDIwT[NHEAD * NEMB];    // [h][e]
__device__ float g_fcNDIwT[NHEAD * NEMB];   // [h][e]
__device__ float g_fc1wT[2 * NEMB * NEMB];  // [c][o]
__device__ float g_l1wT[NEMB * 20];         // [c][o]

__device__ __forceinline__ float elu1(float v) { return v > 0.f ? v : expm1f(v); }

__device__ __forceinline__ unsigned long long pk2(float a, float b) {
    unsigned long long r;
    asm("mov.b64 %0, {%1, %2};" : "=l"(r) : "f"(a), "f"(b));
    return r;
}
__device__ __forceinline__ void upk2(float& a, float& b, unsigned long long v) {
    asm("mov.b64 {%0, %1}, %2;" : "=f"(a), "=f"(b) : "l"(v));
}
// packed dual-FMA via PTX fma.rn.f32x2 (ptxas never auto-fuses)
__device__ __forceinline__ void ffma2(unsigned long long& d, unsigned long long a, unsigned long long b) {
    asm("fma.rn.f32x2 %0, %1, %2, %0;" : "+l"(d) : "l"(a), "l"(b));
}

// ---------------- prep: effective weights + LUT + MLP-weight transposes ----------------
__global__ __launch_bounds__(256) void prep_kernel(const float* __restrict__ wDI,
                                                   const float* __restrict__ wNDI,
                                                   const float* __restrict__ fcDI_w,
                                                   const float* __restrict__ fcNDI_w,
                                                   const float* __restrict__ fc1_w,
                                                   const float* __restrict__ l1_w) {
    __shared__ float w[FMD * FMD];
    int blk = blockIdx.x;
    int tid = threadIdx.x;
    if (blk < NHEAD * SEGS) {
        int h = blk >> 3, seg = blk & (SEGS - 1);
        const float* src = wNDI + h * FMD * FMD;
        for (int i = tid; i < FMD * FMD; i += 256) w[i] = src[i];
        __syncthreads();
        int t0 = seg * SEGLEN, t1 = min(NBIN, t0 + SEGLEN);
        for (int t = t0 + tid; t < t1; t += 256) {
            int I = (int)((147.0f - sqrtf(147.0f * 147.0f - 8.0f * (float)t)) * 0.5f);
            I = max(0, min(72, I));
            while (I > 0 && (I * 73 - (I * (I - 1)) / 2) > t) I--;
            while (I < 72 && ((I + 1) * 73 - ((I + 1) * I) / 2) <= t) I++;
            int J = I + 1 + (t - (I * 73 - (I * (I - 1)) / 2));
            g_wA[t * NHEAD + h] = (w[I * FMD + J] - w[J * FMD + I]) * (1.0f / 16.0f);
            if (h == 0) g_binIJ[t] = (unsigned short)((I << 8) | J);
        }
    } else if (blk < NHEAD * SEGS + NHEAD) {
        int h = blk - NHEAD * SEGS;
        const float* src = wDI + h * FMD * FMD;
        for (int i = tid; i < FMD * FMD; i += 256) w[i] = src[i];
        __syncthreads();
        if (tid < FMD) {
            float cs = 0.f, rs = 0.f;
            #pragma unroll 2
            for (int I = 0; I < FMD; I++) {
                cs += w[I * FMD + tid];
                rs += w[tid * FMD + I];
            }
            g_wDIeff[tid * NHEAD + h] = (cs - rs) * 0.25f;
        }
    } else {
        // MLP weight transposes (one-time, tiny)
        for (int i = tid; i < NHEAD * NEMB; i += 256) {
            int h = i / NEMB, e = i % NEMB;
            g_fcDIwT[i]  = fcDI_w[e * NHEAD + h];
            g_fcNDIwT[i] = fcNDI_w[e * NHEAD + h];
        }
        for (int i = tid; i < 2 * NEMB * NEMB; i += 256) {
            int c = i / NEMB, o = i % NEMB;
            g_fc1wT[i] = fc1_w[o * 2 * NEMB + c];
        }
        for (int i = tid; i < NEMB * 20; i += 256) {
            int c = i / 20, o = i % 20;
            g_l1wT[i] = l1_w[o * NEMB + c];
        }
    }
}

// ---------------- pool: per-row pooled NDI, barrier-free after x load ----------------
__global__ __launch_bounds__(256) void pool_kernel(const float* __restrict__ x) {
    __shared__ __align__(16) float xe[NW];
    int row = blockIdx.x;
    int tid = threadIdx.x;
    const float* xr = x + (size_t)row * 300;
    for (int i = tid; i < NW; i += 256) xe[i] = xr[i] + 5e-6f;   // eps/2 folded
    __syncthreads();
    if (tid < FMD) {
        float4 v = ((const float4*)xe)[tid];
        g_U[row * FMD + tid] = v.x + v.y + v.z + v.w;
    }
    const float4* xs4 = (const float4*)xe;
    for (int b = tid; b < NBINP; b += 256) {
        float acc = 0.f;
        if (b < NBIN) {
            unsigned ij = g_binIJ[b];
            float4 ga = xs4[ij >> 8];
            float4 gb = xs4[ij & 255];
            float av[4] = {ga.x, ga.y, ga.z, ga.w};
            float bv[4] = {gb.x, gb.y, gb.z, gb.w};
            // Sum_i (xj-ai)/(xj+ai) = 2xj * Sum_i 1/s_i - 4  (1 rcp per j)
            acc = -16.0f;
            #pragma unroll
            for (int j = 0; j < 4; j++) {
                float xj = bv[j];
                float s0 = av[0] + xj, s1 = av[1] + xj;
                float s2 = av[2] + xj, s3 = av[3] + xj;
                float t01 = s0 * s1, t23 = s2 * s3;
                float num = fmaf(s0 + s1, t23, (s2 + s3) * t01);
                float den = t01 * t23;
                float y;
                asm("rcp.approx.f32 %0, %1;" : "=f"(y) : "f"(den));
                acc = fmaf(xj + xj, num * y, acc);
            }
        }
        g_P[(size_t)row * NBINP + b] = acc;   // pad bins written as 0 (deterministic)
    }
}

// ---------------- gemm: H = P[2048 x 2816] . wA[2816 x 64], K-split partials ----------------
__global__ __launch_bounds__(256) void gemm_kernel() {
    __shared__ float As[BK][BM + 2];   // +2 keeps u64 alignment, spreads banks
    __shared__ float Bs[BK][BN];
    int tid = threadIdx.x;
    int m0  = blockIdx.x * BM;
    int k0  = blockIdx.y * KLEN;
    // load mapping
    int lrow = tid >> 3;            // 0..31 P-row within tile
    int lcol = (tid & 7) * 4;       // bin within BK
    int lk   = tid >> 3;            // 0..31 wA k
    int lh   = (tid & 7) * 8;       // head
    // compute mapping: 2 rows x 4 heads per thread
    int hg = tid & 15;              // heads 4hg..4hg+3
    int rg = tid >> 4;              // rows 2rg, 2rg+1

    unsigned long long acc0 = 0ull, acc1 = 0ull, acc2 = 0ull, acc3 = 0ull;

    for (int kk = 0; kk < KLEN; kk += BK) {
        float4 pv = *(const float4*)&g_P[(size_t)(m0 + lrow) * NBINP + k0 + kk + lcol];
        float4 w0 = *(const float4*)&g_wA[(size_t)(k0 + kk + lk) * NHEAD + lh];
        float4 w1 = *(const float4*)&g_wA[(size_t)(k0 + kk + lk) * NHEAD + lh + 4];
        __syncthreads();
        As[lcol + 0][lrow] = pv.x;
        As[lcol + 1][lrow] = pv.y;
        As[lcol + 2][lrow] = pv.z;
        As[lcol + 3][lrow] = pv.w;
        *(float4*)&Bs[lk][lh]     = w0;
        *(float4*)&Bs[lk][lh + 4] = w1;
        __syncthreads();
        #pragma unroll
        for (int k = 0; k < BK; k++) {
            unsigned long long a = *(const unsigned long long*)&As[k][2 * rg];  // {r0,r1}
            float4 bv = *(const float4*)&Bs[k][4 * hg];
            ffma2(acc0, a, pk2(bv.x, bv.x));
            ffma2(acc1, a, pk2(bv.y, bv.y));
            ffma2(acc2, a, pk2(bv.z, bv.z));
            ffma2(acc3, a, pk2(bv.w, bv.w));
        }
    }
    float r00, r10, r01, r11, r02, r12, r03, r13;
    upk2(r00, r10, acc0); upk2(r01, r11, acc1);
    upk2(r02, r12, acc2); upk2(r03, r13, acc3);
    size_t base = ((size_t)blockIdx.y * BMAX + m0 + 2 * rg) * NHEAD + 4 * hg;
    *(float4*)&g_Hp[base]         = make_float4(r00, r01, r02, r03);
    *(float4*)&g_Hp[base + NHEAD] = make_float4(r10, r11, r12, r13);
}

// ---------------- tail: partial-reduce + DI head + MLP (coalesced transposed weights) ----------------
struct TailS {
    float hN[RB][NHEAD];
    float hD[RB][NHEAD];
    float emb[RB][2 * NEMB];
    float z1[RB][NEMB];
    float z2[RB][20];
};

__global__ __launch_bounds__(512) void tail_kernel(
    const float* __restrict__ bDI,   const float* __restrict__ fcDI_b,
    const float* __restrict__ bNDI,  const float* __restrict__ fcNDI_b,
    const float* __restrict__ fc1_b, const float* __restrict__ l1_b,
    const float* __restrict__ l2_w,  const float* __restrict__ l2_b,
    float* __restrict__ out)
{
    __shared__ TailS t;
    __shared__ float sus[RB][FMD];
    int tid  = threadIdx.x;
    int row0 = blockIdx.x * RB;

    for (int i = tid; i < RB * FMD; i += 512) {
        int r = i / FMD, K = i % FMD;
        sus[r][K] = g_U[(row0 + r) * FMD + K];
    }
    __syncthreads();

    {   // 512 threads = 8 rows x 64 heads exactly
        int r = tid >> 6, h = tid & 63;
        float s = bNDI[h];
        #pragma unroll
        for (int ks = 0; ks < KSPL; ks++)
            s += g_Hp[((size_t)ks * BMAX + row0 + r) * NHEAD + h];
        t.hN[r][h] = elu1(s);

        float d = 0.f;
        #pragma unroll 2
        for (int K = 0; K < FMD; K++)
            d = fmaf(sus[r][K], g_wDIeff[K * NHEAD + h], d);
        t.hD[r][h] = elu1(d + bDI[h]);
    }
    __syncthreads();

    // eDI / eNDI (48 each) -> emb[96]; wT reads: e lane-varying -> coalesced
    if (tid < RB * NEMB) {
        int r = tid / NEMB, e = tid % NEMB;
        float v = fcDI_b[e], v2 = fcNDI_b[e];
        #pragma unroll 8
        for (int h = 0; h < NHEAD; h++) {
            v  = fmaf(g_fcDIwT[h * NEMB + e],  t.hD[r][h], v);
            v2 = fmaf(g_fcNDIwT[h * NEMB + e], t.hN[r][h], v2);
        }
        t.emb[r][e]        = elu1(v);
        t.emb[r][NEMB + e] = elu1(v2);
    }
    __syncthreads();

    // fc1: 96 -> 48 (o lane-varying -> coalesced)
    if (tid < RB * NEMB) {
        int r = tid / NEMB, o = tid % NEMB;
        float v = fc1_b[o];
        #pragma unroll 8
        for (int c = 0; c < 2 * NEMB; c++) v = fmaf(g_fc1wT[c * NEMB + o], t.emb[r][c], v);
        t.z1[r][o] = elu1(v);
    }
    __syncthreads();

    // l1: 48 -> 20 (o lane-varying -> coalesced)
    if (tid < RB * 20) {
        int r = tid / 20, o = tid % 20;
        float v = l1_b[o];
        #pragma unroll 8
        for (int c = 0; c < NEMB; c++) v = fmaf(g_l1wT[c * 20 + o], t.z1[r][c], v);
        t.z2[r][o] = elu1(v);
    }
    __syncthreads();

    // l2: 20 -> 1, sigmoid
    if (tid < RB) {
        float v = l2_b[0];
        #pragma unroll
        for (int c = 0; c < 20; c++) v = fmaf(l2_w[c], t.z2[tid][c], v);
        out[row0 + tid] = 1.0f / (1.0f + expf(-v));
    }
}

extern "C" void kernel_launch(void* const* d_in, const int* in_sizes, int n_in,
                              void* d_out, int out_size) {
    const float* x       = (const float*)d_in[0];
    const float* wDI     = (const float*)d_in[1];
    const float* bDI     = (const float*)d_in[2];
    const float* fcDI_w  = (const float*)d_in[3];
    const float* fcDI_b  = (const float*)d_in[4];
    const float* wNDI    = (const float*)d_in[5];
    const float* bNDI    = (const float*)d_in[6];
    const float* fcNDI_w = (const float*)d_in[7];
    const float* fcNDI_b = (const float*)d_in[8];
    const float* fc1_w   = (const float*)d_in[9];
    const float* fc1_b   = (const float*)d_in[10];
    const float* l1_w    = (const float*)d_in[11];
    const float* l1_b    = (const float*)d_in[12];
    const float* l2_w    = (const float*)d_in[13];
    const float* l2_b    = (const float*)d_in[14];
    float* out = (float*)d_out;

    int B = in_sizes[0] / 300;   // 2048

    prep_kernel<<<NHEAD * SEGS + NHEAD + 1, 256>>>(wDI, wNDI, fcDI_w, fcNDI_w, fc1_w, l1_w);
    pool_kernel<<<B, 256>>>(x);
    gemm_kernel<<<dim3(B / BM, KSPL), 256>>>();
    tail_kernel<<<B / RB, 512>>>(bDI, fcDI_b, bNDI, fcNDI_b, fc1_b, l1_b, l2_w, l2_b, out);
}

// round 16
// speedup vs baseline: 2.1107x; 1.1653x over previous
#include <cuda_runtime.h>
#include <math.h>

#define NW    296
#define FMD   74
#define NBIN  2701          // 74*73/2
#define NBINP 2816          // 11 * 256 (padded; pad weights stay zero)
#define NHEAD 64
#define NEMB  48
#define RB    8
#define SEGS  8
#define SEGLEN ((NBIN + SEGS - 1) / SEGS)   // 338
#define BMAX  2048
// GEMM tiling
#define BM 32
#define BN 64
#define BK 32
#define KSPL 11
#define KLEN (NBINP / KSPL)   // 256 = 8 BK-steps
#define NSTEP (KLEN / BK)     // 8

// __device__ scratch (zero-initialized at module load)
__device__ float g_wA[NBINP * NHEAD];       // [bin][head] = (wNDI[h,I,J]-wNDI[h,J,I])/16; pads 0
__device__ float g_wDIeff[FMD * NHEAD];     // (colsum-rowsum)/4, K-major
__device__ unsigned short g_binIJ[NBINP];   // (I<<8)|J ; pads 0 (harmless)
__device__ float g_U[BMAX * FMD];           // group sums
__device__ float g_P[BMAX * NBINP];         // pooled NDI (pad values arbitrary but deterministic)
__device__ float g_Hp[KSPL * BMAX * NHEAD]; // GEMM partials
// transposed MLP weights (coalesced tail reads: output index lane-varying)
__device__ float g_fcDIwT[NHEAD * NEMB];    // [h][e]
__device__ float g_fcNDIwT[NHEAD * NEMB];   // [h][e]
__device__ float g_fc1wT[2 * NEMB * NEMB];  // [c][o]
__device__ float g_l1wT[NEMB * 20];         // [c][o]

__device__ __forceinline__ float elu1(float v) { return v > 0.f ? v : expm1f(v); }

__device__ __forceinline__ unsigned long long pk2(float a, float b) {
    unsigned long long r;
    asm("mov.b64 %0, {%1, %2};" : "=l"(r) : "f"(a), "f"(b));
    return r;
}
__device__ __forceinline__ void upk2(float& a, float& b, unsigned long long v) {
    asm("mov.b64 {%0, %1}, %2;" : "=f"(a), "=f"(b) : "l"(v));
}
// packed dual-FMA via PTX fma.rn.f32x2 (ptxas never auto-fuses)
__device__ __forceinline__ void ffma2(unsigned long long& d, unsigned long long a, unsigned long long b) {
    asm("fma.rn.f32x2 %0, %1, %2, %0;" : "+l"(d) : "l"(a), "l"(b));
}

// ---------------- prep: effective weights + LUT + MLP-weight transposes ----------------
__global__ __launch_bounds__(256) void prep_kernel(const float* __restrict__ wDI,
                                                   const float* __restrict__ wNDI,
                                                   const float* __restrict__ fcDI_w,
                                                   const float* __restrict__ fcNDI_w,
                                                   const float* __restrict__ fc1_w,
                                                   const float* __restrict__ l1_w) {
    __shared__ float w[FMD * FMD];
    int blk = blockIdx.x;
    int tid = threadIdx.x;
    if (blk < NHEAD * SEGS) {
        int h = blk >> 3, seg = blk & (SEGS - 1);
        const float* src = wNDI + h * FMD * FMD;
        for (int i = tid; i < FMD * FMD; i += 256) w[i] = src[i];
        __syncthreads();
        int t0 = seg * SEGLEN, t1 = min(NBIN, t0 + SEGLEN);
        for (int t = t0 + tid; t < t1; t += 256) {
            int I = (int)((147.0f - sqrtf(147.0f * 147.0f - 8.0f * (float)t)) * 0.5f);
            I = max(0, min(72, I));
            while (I > 0 && (I * 73 - (I * (I - 1)) / 2) > t) I--;
            while (I < 72 && ((I + 1) * 73 - ((I + 1) * I) / 2) <= t) I++;
            int J = I + 1 + (t - (I * 73 - (I * (I - 1)) / 2));
            g_wA[t * NHEAD + h] = (w[I * FMD + J] - w[J * FMD + I]) * (1.0f / 16.0f);
            if (h == 0) g_binIJ[t] = (unsigned short)((I << 8) | J);
        }
    } else if (blk < NHEAD * SEGS + NHEAD) {
        int h = blk - NHEAD * SEGS;
        const float* src = wDI + h * FMD * FMD;
        for (int i = tid; i < FMD * FMD; i += 256) w[i] = src[i];
        __syncthreads();
        if (tid < FMD) {
            float cs = 0.f, rs = 0.f;
            #pragma unroll 2
            for (int I = 0; I < FMD; I++) {
                cs += w[I * FMD + tid];
                rs += w[tid * FMD + I];
            }
            g_wDIeff[tid * NHEAD + h] = (cs - rs) * 0.25f;
        }
    } else {
        // MLP weight transposes (one-time, tiny)
        for (int i = tid; i < NHEAD * NEMB; i += 256) {
            int h = i / NEMB, e = i % NEMB;
            g_fcDIwT[i]  = fcDI_w[e * NHEAD + h];
            g_fcNDIwT[i] = fcNDI_w[e * NHEAD + h];
        }
        for (int i = tid; i < 2 * NEMB * NEMB; i += 256) {
            int c = i / NEMB, o = i % NEMB;
            g_fc1wT[i] = fc1_w[o * 2 * NEMB + c];
        }
        for (int i = tid; i < NEMB * 20; i += 256) {
            int c = i / 20, o = i % 20;
            g_l1wT[i] = l1_w[o * NEMB + c];
        }
    }
}

// ---------------- pool: per-row pooled NDI; 11 fully-unrolled guard-free bins/thread ----------------
__global__ __launch_bounds__(256) void pool_kernel(const float* __restrict__ x) {
    __shared__ __align__(16) float xe[NW];
    int row = blockIdx.x;
    int tid = threadIdx.x;
    const float* xr = x + (size_t)row * 300;
    for (int i = tid; i < NW; i += 256) xe[i] = xr[i] + 5e-6f;   // eps/2 folded
    __syncthreads();
    if (tid < FMD) {
        float4 v = ((const float4*)xe)[tid];
        g_U[row * FMD + tid] = v.x + v.y + v.z + v.w;
    }
    const float4* xs4 = (const float4*)xe;
    float* Pr = g_P + (size_t)row * NBINP;
    #pragma unroll
    for (int it = 0; it < 11; it++) {
        int b = tid + it * 256;           // NBINP = 11*256 exactly; pad bins compute
        unsigned ij = g_binIJ[b];         // garbage that gemm multiplies by zero wA
        float4 ga = xs4[ij >> 8];
        float4 gb = xs4[ij & 255];
        float av[4] = {ga.x, ga.y, ga.z, ga.w};
        float bv[4] = {gb.x, gb.y, gb.z, gb.w};
        // Sum_i (xj-ai)/(xj+ai) = 2xj * Sum_i 1/s_i - 4  (1 rcp per j)
        float acc = -16.0f;
        #pragma unroll
        for (int j = 0; j < 4; j++) {
            float xj = bv[j];
            float s0 = av[0] + xj, s1 = av[1] + xj;
            float s2 = av[2] + xj, s3 = av[3] + xj;
            float t01 = s0 * s1, t23 = s2 * s3;
            float num = fmaf(s0 + s1, t23, (s2 + s3) * t01);
            float den = t01 * t23;
            float y;
            asm("rcp.approx.f32 %0, %1;" : "=f"(y) : "f"(den));
            acc = fmaf(xj + xj, num * y, acc);
        }
        Pr[b] = acc;
    }
}

// ---------------- gemm: H = P . wA, double-buffered, 1 barrier per BK-step ----------------
__global__ __launch_bounds__(256) void gemm_kernel() {
    __shared__ float As[2][BK][BM + 2];
    __shared__ float Bs[2][BK][BN];
    int tid = threadIdx.x;
    int m0  = blockIdx.x * BM;
    int k0  = blockIdx.y * KLEN;
    int lrow = tid >> 3;            // 0..31 P-row within tile
    int lcol = (tid & 7) * 4;       // bin within BK
    int lk   = tid >> 3;            // 0..31 wA k
    int lh   = (tid & 7) * 8;       // head
    int hg = tid & 15;              // heads 4hg..4hg+3
    int rg = tid >> 4;              // rows 2rg, 2rg+1

    unsigned long long acc0 = 0ull, acc1 = 0ull, acc2 = 0ull, acc3 = 0ull;

    // prologue: load step 0
    float4 pv = *(const float4*)&g_P[(size_t)(m0 + lrow) * NBINP + k0 + lcol];
    float4 w0 = *(const float4*)&g_wA[(size_t)(k0 + lk) * NHEAD + lh];
    float4 w1 = *(const float4*)&g_wA[(size_t)(k0 + lk) * NHEAD + lh + 4];
    As[0][lcol + 0][lrow] = pv.x;
    As[0][lcol + 1][lrow] = pv.y;
    As[0][lcol + 2][lrow] = pv.z;
    As[0][lcol + 3][lrow] = pv.w;
    *(float4*)&Bs[0][lk][lh]     = w0;
    *(float4*)&Bs[0][lk][lh + 4] = w1;
    __syncthreads();

    #pragma unroll
    for (int s = 0; s < NSTEP; s++) {
        int cur = s & 1;
        if (s + 1 < NSTEP) {   // prefetch next tile (overlaps compute)
            int kk = (s + 1) * BK;
            pv = *(const float4*)&g_P[(size_t)(m0 + lrow) * NBINP + k0 + kk + lcol];
            w0 = *(const float4*)&g_wA[(size_t)(k0 + kk + lk) * NHEAD + lh];
            w1 = *(const float4*)&g_wA[(size_t)(k0 + kk + lk) * NHEAD + lh + 4];
        }
        #pragma unroll
        for (int k = 0; k < BK; k++) {
            unsigned long long a = *(const unsigned long long*)&As[cur][k][2 * rg];  // {r0,r1}
            float4 bv = *(const float4*)&Bs[cur][k][4 * hg];
            ffma2(acc0, a, pk2(bv.x, bv.x));
            ffma2(acc1, a, pk2(bv.y, bv.y));
            ffma2(acc2, a, pk2(bv.z, bv.z));
            ffma2(acc3, a, pk2(bv.w, bv.w));
        }
        if (s + 1 < NSTEP) {
            int nxt = cur ^ 1;   // last read of buf[nxt] was compute(s-1), fenced by prior sync
            As[nxt][lcol + 0][lrow] = pv.x;
            As[nxt][lcol + 1][lrow] = pv.y;
            As[nxt][lcol + 2][lrow] = pv.z;
            As[nxt][lcol + 3][lrow] = pv.w;
            *(float4*)&Bs[nxt][lk][lh]     = w0;
            *(float4*)&Bs[nxt][lk][lh + 4] = w1;
            __syncthreads();
        }
    }
    float r00, r10, r01, r11, r02, r12, r03, r13;
    upk2(r00, r10, acc0); upk2(r01, r11, acc1);
    upk2(r02, r12, acc2); upk2(r03, r13, acc3);
    size_t base = ((size_t)blockIdx.y * BMAX + m0 + 2 * rg) * NHEAD + 4 * hg;
    *(float4*)&g_Hp[base]         = make_float4(r00, r01, r02, r03);
    *(float4*)&g_Hp[base + NHEAD] = make_float4(r10, r11, r12, r13);
}

// ---------------- tail: partial-reduce + DI head + MLP, multi-accumulator ILP ----------------
struct TailS {
    float hN[RB][NHEAD];
    float hD[RB][NHEAD];
    float emb[RB][2 * NEMB];
    float z1[RB][NEMB];
    float z2[RB][20];
};

__global__ __launch_bounds__(512) void tail_kernel(
    const float* __restrict__ bDI,   const float* __restrict__ fcDI_b,
    const float* __restrict__ bNDI,  const float* __restrict__ fcNDI_b,
    const float* __restrict__ fc1_b, const float* __restrict__ l1_b,
    const float* __restrict__ l2_w,  const float* __restrict__ l2_b,
    float* __restrict__ out)
{
    __shared__ TailS t;
    __shared__ float sus[RB][FMD];
    int tid  = threadIdx.x;
    int row0 = blockIdx.x * RB;

    for (int i = tid; i < RB * FMD; i += 512) {
        int r = i / FMD, K = i % FMD;
        sus[r][K] = g_U[(row0 + r) * FMD + K];
    }
    __syncthreads();

    {   // 512 threads = 8 rows x 64 heads; 2-chain ILP everywhere
        int r = tid >> 6, h = tid & 63;
        size_t hb = (size_t)(row0 + r) * NHEAD + h;
        float s0 = bNDI[h], s1 = 0.f;
        #pragma unroll
        for (int ks = 0; ks < 10; ks += 2) {
            s0 += g_Hp[(size_t)ks * BMAX * NHEAD + hb];
            s1 += g_Hp[(size_t)(ks + 1) * BMAX * NHEAD + hb];
        }
        s0 += g_Hp[(size_t)10 * BMAX * NHEAD + hb];
        t.hN[r][h] = elu1(s0 + s1);

        float d0 = 0.f, d1 = 0.f;
        #pragma unroll
        for (int K = 0; K < 37; K++) {
            d0 = fmaf(sus[r][K],      g_wDIeff[K * NHEAD + h],        d0);
            d1 = fmaf(sus[r][K + 37], g_wDIeff[(K + 37) * NHEAD + h], d1);
        }
        t.hD[r][h] = elu1(d0 + d1 + bDI[h]);
    }
    __syncthreads();

    // eDI / eNDI -> emb[96]; 4 independent chains
    if (tid < RB * NEMB) {
        int r = tid / NEMB, e = tid % NEMB;
        float v0 = fcDI_b[e],  v1 = 0.f;
        float u0 = fcNDI_b[e], u1 = 0.f;
        #pragma unroll 8
        for (int h = 0; h < 32; h++) {
            v0 = fmaf(g_fcDIwT[h * NEMB + e],         t.hD[r][h],      v0);
            v1 = fmaf(g_fcDIwT[(h + 32) * NEMB + e],  t.hD[r][h + 32], v1);
            u0 = fmaf(g_fcNDIwT[h * NEMB + e],        t.hN[r][h],      u0);
            u1 = fmaf(g_fcNDIwT[(h + 32) * NEMB + e], t.hN[r][h + 32], u1);
        }
        t.emb[r][e]        = elu1(v0 + v1);
        t.emb[r][NEMB + e] = elu1(u0 + u1);
    }
    __syncthreads();

    // fc1: 96 -> 48; 2 chains
    if (tid < RB * NEMB) {
        int r = tid / NEMB, o = tid % NEMB;
        float v0 = fc1_b[o], v1 = 0.f;
        #pragma unroll 8
        for (int c = 0; c < NEMB; c++) {
            v0 = fmaf(g_fc1wT[c * NEMB + o],          t.emb[r][c],        v0);
            v1 = fmaf(g_fc1wT[(c + NEMB) * NEMB + o], t.emb[r][c + NEMB], v1);
        }
        t.z1[r][o] = elu1(v0 + v1);
    }
    __syncthreads();

    // l1: 48 -> 20; 2 chains
    if (tid < RB * 20) {
        int r = tid / 20, o = tid % 20;
        float v0 = l1_b[o], v1 = 0.f;
        #pragma unroll 8
        for (int c = 0; c < 24; c++) {
            v0 = fmaf(g_l1wT[c * 20 + o],        t.z1[r][c],      v0);
            v1 = fmaf(g_l1wT[(c + 24) * 20 + o], t.z1[r][c + 24], v1);
        }
        t.z2[r][o] = elu1(v0 + v1);
    }
    __syncthreads();

    // l2: 20 -> 1, sigmoid
    if (tid < RB) {
        float v = l2_b[0];
        #pragma unroll
        for (int c = 0; c < 20; c++) v = fmaf(l2_w[c], t.z2[tid][c], v);
        out[row0 + tid] = 1.0f / (1.0f + expf(-v));
    }
}

extern "C" void kernel_launch(void* const* d_in, const int* in_sizes, int n_in,
                              void* d_out, int out_size) {
    const float* x       = (const float*)d_in[0];
    const float* wDI     = (const float*)d_in[1];
    const float* bDI     = (const float*)d_in[2];
    const float* fcDI_w  = (const float*)d_in[3];
    const float* fcDI_b  = (const float*)d_in[4];
    const float* wNDI    = (const float*)d_in[5];
    const float* bNDI    = (const float*)d_in[6];
    const float* fcNDI_w = (const float*)d_in[7];
    const float* fcNDI_b = (const float*)d_in[8];
    const float* fc1_w   = (const float*)d_in[9];
    const float* fc1_b   = (const float*)d_in[10];
    const float* l1_w    = (const float*)d_in[11];
    const float* l1_b    = (const float*)d_in[12];
    const float* l2_w    = (const float*)d_in[13];
    const float* l2_b    = (const float*)d_in[14];
    float* out = (float*)d_out;

    int B = in_sizes[0] / 300;   // 2048

    prep_kernel<<<NHEAD * SEGS + NHEAD + 1, 256>>>(wDI, wNDI, fcDI_w, fcNDI_w, fc1_w, l1_w);
    pool_kernel<<<B, 256>>>(x);
    gemm_kernel<<<dim3(B / BM, KSPL), 256>>>();
    tail_kernel<<<B / RB, 512>>>(bDI, fcDI_b, bNDI, fcNDI_b, fc1_b, l1_b, l2_w, l2_b, out);
}